// round 11
// baseline (speedup 1.0000x reference)
#include <cuda_runtime.h>

#define BB   32
#define HW_  1600
#define A_   5
#define NGT  128
#define CC   80
#define TPB  160   // preds per block; 50 blocks per batch

constexpr int NPRED       = BB * HW_ * A_;            // 256000
constexpr int IOUS_OFF    = NPRED * 4;
constexpr int CLASSES_OFF = IOUS_OFF + NPRED;
constexpr int BOXM_OFF    = CLASSES_OFF + NPRED * CC;
constexpr int IOUM_OFF    = BOXM_OFF + NPRED;
constexpr int CLSM_OFF    = IOUM_OFF + NPRED;

// ---------------------------------------------------------------------------
// Fused kernel v8 — exact round-8 structure (best kernel time, 20.8us) with
// ONE change: __launch_bounds__(TPB, 12) caps regs at 34 -> 12 blocks/SM
// (60 warps, 94% occ ceiling vs 78% before) to cover the latency exposure
// ncu shows (issue 31%, all pipes <45%).
// ---------------------------------------------------------------------------
__global__ void __launch_bounds__(TPB, 12) yolo_fused_kernel(
    const float4* __restrict__ bbox_pred,
    const float*  __restrict__ iou_pred,
    const float*  __restrict__ gt,        // BB * NGT * 5
    const float*  __restrict__ anchors,   // 5*2
    const int*    __restrict__ num_boxes, // BB
    float*        __restrict__ out)
{
    __shared__ float4 g4[NGT];     // x1, y1, x2+1, y2+1
    __shared__ float  sg[NGT];     // 0.375 * garea
    __shared__ float  sga[NGT];    // garea
    __shared__ float4 stbox[NGT];  // target tbox per gt
    __shared__ int    swin[TPB];   // winning gt index per local pred slot

    const int tid = threadIdx.x;
    const int t0  = blockIdx.x * TPB;
    const int t   = t0 + tid;
    const int b   = blockIdx.x / 50;
    const int lane = tid & 31;

    // ---- early loads (latency overlapped by the store burst below) ----
    const float4 bp = bbox_pred[t];
    const float  ip = iou_pred[t];

    // ---- phase 0: default-store burst (no dependencies, issued first) ----
    float4* out4 = (float4*)out;
    {
        const long cbase = (long)(CLASSES_OFF / 4) + (long)(t >> 5) * (32 * 20);
        const float4 z = make_float4(0.f, 0.f, 0.f, 0.f);
        #pragma unroll
        for (int i = 0; i < 20; i++)
            out4[cbase + (long)i * 32 + lane] = z;       // classes = 0
    }
    out4[t] = make_float4(0.5f, 0.5f, 1.0f, 1.0f);       // boxes_t default
    out[IOUS_OFF + t] = 0.0f;                            // ious_t
    out[BOXM_OFF + t] = 0.01f;                           // box_mask
    out[CLSM_OFF + t] = 0.0f;                            // class_mask
    out[IOUM_OFF + t] = -ip;                             // iou_mask default

    swin[tid] = -1;

    // ---- phase A: gt metadata (tid < 128) ----
    int  my_flat = 0, my_local = -1, my_cls = 0;
    bool my_valid = false;
    if (tid < NGT) {
        const float* p = gt + ((long)b * NGT + tid) * 5;
        const float gx1 = p[0], gy1 = p[1], gx2 = p[2], gy2 = p[3];
        my_cls = (int)p[4];
        g4[tid] = make_float4(gx1, gy1, gx2 + 1.0f, gy2 + 1.0f);
        const float ga = (gx2 - gx1 + 1.0f) * (gy2 - gy1 + 1.0f);
        sga[tid] = ga;
        sg[tid]  = 0.375f * ga;

        const float cx = (gx1 + gx2) * 0.5f / 32.0f;
        const float cy = (gy1 + gy2) * 0.5f / 32.0f;
        const float fcx = floorf(cx), fcy = floorf(cy);
        const int cell = (int)(fcy * 40.0f + fcx);
        const int nb = num_boxes[b];
        my_valid = (tid < nb) && (cell >= 0) && (cell < HW_);

        // anchor argmax (first max wins)
        const float gw = (gx2 / 32.0f - gx1 / 32.0f) + 1.0f;
        const float gh = (gy2 / 32.0f - gy1 / 32.0f) + 1.0f;
        const float gwh = gw * gh;
        int a_ind = 0;
        float bestA = -1.0f;
        #pragma unroll
        for (int a = 0; a < A_; a++) {
            const float aw = anchors[2 * a], ah = anchors[2 * a + 1];
            const float inta = fminf(aw, gw) * fminf(ah, gh);
            const float aiou = inta / (aw * ah + gwh - inta);
            if (aiou > bestA) { bestA = aiou; a_ind = a; }
        }

        my_flat  = (b * HW_ + cell) * A_ + a_ind;
        my_local = my_flat - t0;
        const float tw = (gx2 - gx1 + 1.0f) / 32.0f;
        const float th = (gy2 - gy1 + 1.0f) / 32.0f;
        stbox[tid] = make_float4(cx - fcx, cy - fcy,
                                 tw / anchors[2 * a_ind],
                                 th / anchors[2 * a_ind + 1]);
    }
    __syncthreads();

    // ---- phase B: scatter ownership (last index wins -> max n) ----
    if (tid < NGT && my_valid && my_local >= 0 && my_local < TPB)
        atomicMax(&swin[my_local], tid);
    __syncthreads();

    // ---- classes 1.0-set: barrier-ordered after this block's zero stores ----
    if (tid < NGT && my_valid && my_local >= 0 && my_local < TPB)
        out[CLASSES_OFF + (long)my_flat * CC + my_cls] = 1.0f;

    // ---- phase C: pred geometry ----
    const int hw = (t / A_) % HW_;
    const int a  = t % A_;
    const float col = (float)(hw % 40);
    const float row = (float)(hw / 40);
    const float cxp = (bp.x + col) * (1.0f / 40.0f);
    const float cyp = (bp.y + row) * (1.0f / 40.0f);
    const float bw  = bp.z * anchors[2 * a]     * (1.0f / 40.0f) * 0.5f;
    const float bh  = bp.w * anchors[2 * a + 1] * (1.0f / 40.0f) * 0.5f;
    const float x1  = (cxp - bw) * 1280.0f;
    const float y1  = (cyp - bh) * 1280.0f;
    const float x2p = (cxp + bw) * 1280.0f + 1.0f;
    const float y2p = (cyp + bh) * 1280.0f + 1.0f;
    const float sb  = 0.375f * (x2p - x1) * (y2p - y1);

    // ---- warp hull of the 32 pred boxes ----
    float hx1 = x1, hy1 = y1, hx2 = x2p, hy2 = y2p;
    #pragma unroll
    for (int s = 16; s; s >>= 1) {
        hx1 = fminf(hx1, __shfl_xor_sync(0xffffffffu, hx1, s));
        hy1 = fminf(hy1, __shfl_xor_sync(0xffffffffu, hy1, s));
        hx2 = fmaxf(hx2, __shfl_xor_sync(0xffffffffu, hx2, s));
        hy2 = fmaxf(hy2, __shfl_xor_sync(0xffffffffu, hy2, s));
    }

    // ---- candidate masks via ballot ----
    unsigned masks[4];
    #pragma unroll
    for (int j = 0; j < 4; j++) {
        const float4 g = g4[j * 32 + lane];
        const bool cand = (fminf(hx2, g.z) > fmaxf(hx1, g.x)) &&
                          (fminf(hy2, g.w) > fmaxf(hy1, g.y));
        masks[j] = __ballot_sync(0xffffffffu, cand);
    }

    // ---- hit loop over candidates only ----
    float acc = -1e30f;
    #pragma unroll
    for (int j = 0; j < 4; j++) {
        unsigned m = masks[j];
        while (m) {
            const int n = j * 32 + (__ffs(m) - 1);
            m &= m - 1;
            const float4 g = g4[n];
            const float iw = fmaxf(fminf(x2p, g.z) - fmaxf(x1, g.x), 0.0f);
            const float ih = fminf(y2p, g.w) - fmaxf(y1, g.y);
            acc = fmaxf(acc, fmaf(iw, ih, -sg[n]));
        }
    }
    const bool hit = (acc >= sb);

    // ---- fix-ups (same thread as the default writes -> ordered) ----
    const int win = swin[tid];
    if (win >= 0) {
        const float4 g = g4[win];
        const float iw = fmaxf(fminf(x2p, g.z) - fmaxf(x1, g.x), 0.0f);
        const float ih = fmaxf(fminf(y2p, g.w) - fmaxf(y1, g.y), 0.0f);
        const float inter = iw * ih;
        const float ba = (x2p - x1) * (y2p - y1);
        const float iou = inter / (ba + sga[win] - inter);
        out4[t] = stbox[win];
        out[IOUS_OFF + t] = iou;
        out[BOXM_OFF + t] = 1.0f;
        out[IOUM_OFF + t] = 5.0f * (1.0f - ip);
        out[CLSM_OFF + t] = 1.0f;
    } else if (hit) {
        out[IOUM_OFF + t] = 0.0f;
    }
}

extern "C" void kernel_launch(void* const* d_in, const int* in_sizes, int n_in,
                              void* d_out, int out_size)
{
    const float4* bbox4   = (const float4*)d_in[0];
    const float*  ioup    = (const float*)d_in[1];
    const float*  gtb     = (const float*)d_in[2];
    const float*  anchors = (const float*)d_in[3];
    const int*    nboxes  = (const int*)d_in[4];
    float* out = (float*)d_out;

    yolo_fused_kernel<<<NPRED / TPB, TPB>>>(bbox4, ioup, gtb, anchors, nboxes, out);
}

// round 12
// speedup vs baseline: 1.1860x; 1.1860x over previous
#include <cuda_runtime.h>

#define BB   32
#define HW_  1600
#define A_   5
#define NGT  128
#define CC   80
#define TPB  160   // preds per block; 50 blocks per batch (round-8 proven config)

constexpr int NPRED       = BB * HW_ * A_;            // 256000
constexpr int IOUS_OFF    = NPRED * 4;
constexpr int CLASSES_OFF = IOUS_OFF + NPRED;
constexpr int BOXM_OFF    = CLASSES_OFF + NPRED * CC;
constexpr int IOUM_OFF    = BOXM_OFF + NPRED;
constexpr int CLSM_OFF    = IOUM_OFF + NPRED;

// ---------------------------------------------------------------------------
// Fused kernel v9 — exact round-8 structure (best kernel time, 20.8us), with
// streaming (evict-first) stores for the 86MB default burst so dirty-line
// writeback overlaps the kernel instead of serializing between graph replays,
// and inputs stay L2-resident across replays.
// ---------------------------------------------------------------------------
__global__ void __launch_bounds__(TPB) yolo_fused_kernel(
    const float4* __restrict__ bbox_pred,
    const float*  __restrict__ iou_pred,
    const float*  __restrict__ gt,        // BB * NGT * 5
    const float*  __restrict__ anchors,   // 5*2
    const int*    __restrict__ num_boxes, // BB
    float*        __restrict__ out)
{
    __shared__ float4 g4[NGT];     // x1, y1, x2+1, y2+1
    __shared__ float  sg[NGT];     // 0.375 * garea
    __shared__ float  sga[NGT];    // garea
    __shared__ float4 stbox[NGT];  // target tbox per gt
    __shared__ int    swin[TPB];   // winning gt index per local pred slot

    const int tid = threadIdx.x;
    const int t0  = blockIdx.x * TPB;
    const int t   = t0 + tid;
    const int b   = blockIdx.x / 50;
    const int lane = tid & 31;

    // ---- early loads (latency overlapped by the store burst below) ----
    const float4 bp = bbox_pred[t];
    const float  ip = iou_pred[t];

    // ---- phase 0: default-store burst, streaming/evict-first ----
    float4* out4 = (float4*)out;
    {
        const long cbase = (long)(CLASSES_OFF / 4) + (long)(t >> 5) * (32 * 20);
        const float4 z = make_float4(0.f, 0.f, 0.f, 0.f);
        #pragma unroll
        for (int i = 0; i < 20; i++)
            __stcs(&out4[cbase + (long)i * 32 + lane], z);   // classes = 0
    }
    __stcs(&out4[t], make_float4(0.5f, 0.5f, 1.0f, 1.0f));   // boxes_t default
    __stcs(&out[IOUS_OFF + t], 0.0f);                        // ious_t
    __stcs(&out[BOXM_OFF + t], 0.01f);                       // box_mask
    __stcs(&out[CLSM_OFF + t], 0.0f);                        // class_mask
    __stcs(&out[IOUM_OFF + t], -ip);                         // iou_mask default

    swin[tid] = -1;

    // ---- phase A: gt metadata (tid < 128) ----
    int  my_flat = 0, my_local = -1, my_cls = 0;
    bool my_valid = false;
    if (tid < NGT) {
        const float* p = gt + ((long)b * NGT + tid) * 5;
        const float gx1 = p[0], gy1 = p[1], gx2 = p[2], gy2 = p[3];
        my_cls = (int)p[4];
        g4[tid] = make_float4(gx1, gy1, gx2 + 1.0f, gy2 + 1.0f);
        const float ga = (gx2 - gx1 + 1.0f) * (gy2 - gy1 + 1.0f);
        sga[tid] = ga;
        sg[tid]  = 0.375f * ga;

        const float cx = (gx1 + gx2) * 0.5f / 32.0f;
        const float cy = (gy1 + gy2) * 0.5f / 32.0f;
        const float fcx = floorf(cx), fcy = floorf(cy);
        const int cell = (int)(fcy * 40.0f + fcx);
        const int nb = num_boxes[b];
        my_valid = (tid < nb) && (cell >= 0) && (cell < HW_);

        // anchor argmax (first max wins)
        const float gw = (gx2 / 32.0f - gx1 / 32.0f) + 1.0f;
        const float gh = (gy2 / 32.0f - gy1 / 32.0f) + 1.0f;
        const float gwh = gw * gh;
        int a_ind = 0;
        float bestA = -1.0f;
        #pragma unroll
        for (int a = 0; a < A_; a++) {
            const float aw = anchors[2 * a], ah = anchors[2 * a + 1];
            const float inta = fminf(aw, gw) * fminf(ah, gh);
            const float aiou = inta / (aw * ah + gwh - inta);
            if (aiou > bestA) { bestA = aiou; a_ind = a; }
        }

        my_flat  = (b * HW_ + cell) * A_ + a_ind;
        my_local = my_flat - t0;
        const float tw = (gx2 - gx1 + 1.0f) / 32.0f;
        const float th = (gy2 - gy1 + 1.0f) / 32.0f;
        stbox[tid] = make_float4(cx - fcx, cy - fcy,
                                 tw / anchors[2 * a_ind],
                                 th / anchors[2 * a_ind + 1]);
    }
    __syncthreads();

    // ---- phase B: scatter ownership (last index wins -> max n) ----
    if (tid < NGT && my_valid && my_local >= 0 && my_local < TPB)
        atomicMax(&swin[my_local], tid);
    __syncthreads();

    // ---- classes 1.0-set: barrier-ordered after this block's zero stores ----
    if (tid < NGT && my_valid && my_local >= 0 && my_local < TPB)
        out[CLASSES_OFF + (long)my_flat * CC + my_cls] = 1.0f;

    // ---- phase C: pred geometry ----
    const int hw = (t / A_) % HW_;
    const int a  = t % A_;
    const float col = (float)(hw % 40);
    const float row = (float)(hw / 40);
    const float cxp = (bp.x + col) * (1.0f / 40.0f);
    const float cyp = (bp.y + row) * (1.0f / 40.0f);
    const float bw  = bp.z * anchors[2 * a]     * (1.0f / 40.0f) * 0.5f;
    const float bh  = bp.w * anchors[2 * a + 1] * (1.0f / 40.0f) * 0.5f;
    const float x1  = (cxp - bw) * 1280.0f;
    const float y1  = (cyp - bh) * 1280.0f;
    const float x2p = (cxp + bw) * 1280.0f + 1.0f;
    const float y2p = (cyp + bh) * 1280.0f + 1.0f;
    const float sb  = 0.375f * (x2p - x1) * (y2p - y1);

    // ---- warp hull of the 32 pred boxes ----
    float hx1 = x1, hy1 = y1, hx2 = x2p, hy2 = y2p;
    #pragma unroll
    for (int s = 16; s; s >>= 1) {
        hx1 = fminf(hx1, __shfl_xor_sync(0xffffffffu, hx1, s));
        hy1 = fminf(hy1, __shfl_xor_sync(0xffffffffu, hy1, s));
        hx2 = fmaxf(hx2, __shfl_xor_sync(0xffffffffu, hx2, s));
        hy2 = fmaxf(hy2, __shfl_xor_sync(0xffffffffu, hy2, s));
    }

    // ---- candidate masks via ballot ----
    unsigned masks[4];
    #pragma unroll
    for (int j = 0; j < 4; j++) {
        const float4 g = g4[j * 32 + lane];
        const bool cand = (fminf(hx2, g.z) > fmaxf(hx1, g.x)) &&
                          (fminf(hy2, g.w) > fmaxf(hy1, g.y));
        masks[j] = __ballot_sync(0xffffffffu, cand);
    }

    // ---- hit loop over candidates only ----
    float acc = -1e30f;
    #pragma unroll
    for (int j = 0; j < 4; j++) {
        unsigned m = masks[j];
        while (m) {
            const int n = j * 32 + (__ffs(m) - 1);
            m &= m - 1;
            const float4 g = g4[n];
            const float iw = fmaxf(fminf(x2p, g.z) - fmaxf(x1, g.x), 0.0f);
            const float ih = fminf(y2p, g.w) - fmaxf(y1, g.y);
            acc = fmaxf(acc, fmaf(iw, ih, -sg[n]));
        }
    }
    const bool hit = (acc >= sb);

    // ---- fix-ups (same thread as the default writes -> ordered) ----
    const int win = swin[tid];
    if (win >= 0) {
        const float4 g = g4[win];
        const float iw = fmaxf(fminf(x2p, g.z) - fmaxf(x1, g.x), 0.0f);
        const float ih = fmaxf(fminf(y2p, g.w) - fmaxf(y1, g.y), 0.0f);
        const float inter = iw * ih;
        const float ba = (x2p - x1) * (y2p - y1);
        const float iou = inter / (ba + sga[win] - inter);
        out4[t] = stbox[win];
        out[IOUS_OFF + t] = iou;
        out[BOXM_OFF + t] = 1.0f;
        out[IOUM_OFF + t] = 5.0f * (1.0f - ip);
        out[CLSM_OFF + t] = 1.0f;
    } else if (hit) {
        out[IOUM_OFF + t] = 0.0f;
    }
}

extern "C" void kernel_launch(void* const* d_in, const int* in_sizes, int n_in,
                              void* d_out, int out_size)
{
    const float4* bbox4   = (const float4*)d_in[0];
    const float*  ioup    = (const float*)d_in[1];
    const float*  gtb     = (const float*)d_in[2];
    const float*  anchors = (const float*)d_in[3];
    const int*    nboxes  = (const int*)d_in[4];
    float* out = (float*)d_out;

    yolo_fused_kernel<<<NPRED / TPB, TPB>>>(bbox4, ioup, gtb, anchors, nboxes, out);
}

// round 13
// speedup vs baseline: 1.4349x; 1.2098x over previous
#include <cuda_runtime.h>
#include <cstdint>

#define BB   32
#define HW_  1600
#define A_   5
#define NGT  128
#define CC   80
#define TPB  160   // preds per block; 50 blocks per batch

constexpr int NPRED       = BB * HW_ * A_;            // 256000
constexpr int IOUS_OFF    = NPRED * 4;
constexpr int CLASSES_OFF = IOUS_OFF + NPRED;
constexpr int BOXM_OFF    = CLASSES_OFF + NPRED * CC;
constexpr int IOUM_OFF    = BOXM_OFF + NPRED;
constexpr int CLSM_OFF    = IOUM_OFF + NPRED;

constexpr int CLS_SLICE_BYTES = TPB * CC * 4;   // 51200 per block
constexpr int STAGE_FLOATS    = 3200;           // 12800 B zero staging
constexpr int STAGE_BYTES     = STAGE_FLOATS * 4;
constexpr int NBULK           = CLS_SLICE_BYTES / STAGE_BYTES;  // 4

// ---------------------------------------------------------------------------
// Fused kernel v10 — round-12 structure (best: 19.9us kernel / 22.9us dur),
// with the classes zero-fill moved OFF the LSU: a 12.8KB all-zero SMEM buffer
// sources 4 TMA bulk stores covering the block's 51.2KB classes slice
// (buffer never changes, so one small buffer serves all 4 -> occupancy kept,
// unlike round 7's 100KB staging). ~20 STG.128/thread removed; TMA drains
// under the hit loop. 1.0-fixup ordered via wait_group + barrier.
// ---------------------------------------------------------------------------
__global__ void __launch_bounds__(TPB) yolo_fused_kernel(
    const float4* __restrict__ bbox_pred,
    const float*  __restrict__ iou_pred,
    const float*  __restrict__ gt,        // BB * NGT * 5
    const float*  __restrict__ anchors,   // 5*2
    const int*    __restrict__ num_boxes, // BB
    float*        __restrict__ out)
{
    __shared__ __align__(16) float stage[STAGE_FLOATS];  // stays all-zero
    __shared__ float4 g4[NGT];     // x1, y1, x2+1, y2+1
    __shared__ float  sg[NGT];     // 0.375 * garea
    __shared__ float  sga[NGT];    // garea
    __shared__ float4 stbox[NGT];  // target tbox per gt
    __shared__ int    swin[TPB];   // winning gt index per local pred slot

    const int tid = threadIdx.x;
    const int t0  = blockIdx.x * TPB;
    const int t   = t0 + tid;
    const int b   = blockIdx.x / 50;
    const int lane = tid & 31;

    // ---- early loads ----
    const float4 bp = bbox_pred[t];
    const float  ip = iou_pred[t];

    // ---- zero the (reusable) staging buffer: 5 STS.128 per thread ----
    {
        float4* s4 = (float4*)stage;
        const float4 z = make_float4(0.f, 0.f, 0.f, 0.f);
        #pragma unroll
        for (int i = 0; i < 5; i++)
            s4[i * TPB + tid] = z;
    }

    // ---- small default stores (streaming) ----
    float4* out4 = (float4*)out;
    __stcs(&out4[t], make_float4(0.5f, 0.5f, 1.0f, 1.0f));   // boxes_t default
    __stcs(&out[IOUS_OFF + t], 0.0f);                        // ious_t
    __stcs(&out[BOXM_OFF + t], 0.01f);                       // box_mask
    __stcs(&out[CLSM_OFF + t], 0.0f);                        // class_mask
    __stcs(&out[IOUM_OFF + t], -ip);                         // iou_mask default

    swin[tid] = -1;

    // ---- phase A: gt metadata (tid < 128) ----
    int  my_flat = 0, my_local = -1, my_cls = 0;
    bool my_valid = false;
    if (tid < NGT) {
        const float* p = gt + ((long)b * NGT + tid) * 5;
        const float gx1 = p[0], gy1 = p[1], gx2 = p[2], gy2 = p[3];
        my_cls = (int)p[4];
        g4[tid] = make_float4(gx1, gy1, gx2 + 1.0f, gy2 + 1.0f);
        const float ga = (gx2 - gx1 + 1.0f) * (gy2 - gy1 + 1.0f);
        sga[tid] = ga;
        sg[tid]  = 0.375f * ga;

        const float cx = (gx1 + gx2) * 0.5f / 32.0f;
        const float cy = (gy1 + gy2) * 0.5f / 32.0f;
        const float fcx = floorf(cx), fcy = floorf(cy);
        const int cell = (int)(fcy * 40.0f + fcx);
        const int nb = num_boxes[b];
        my_valid = (tid < nb) && (cell >= 0) && (cell < HW_);

        // anchor argmax (first max wins)
        const float gw = (gx2 / 32.0f - gx1 / 32.0f) + 1.0f;
        const float gh = (gy2 / 32.0f - gy1 / 32.0f) + 1.0f;
        const float gwh = gw * gh;
        int a_ind = 0;
        float bestA = -1.0f;
        #pragma unroll
        for (int a = 0; a < A_; a++) {
            const float aw = anchors[2 * a], ah = anchors[2 * a + 1];
            const float inta = fminf(aw, gw) * fminf(ah, gh);
            const float aiou = inta / (aw * ah + gwh - inta);
            if (aiou > bestA) { bestA = aiou; a_ind = a; }
        }

        my_flat  = (b * HW_ + cell) * A_ + a_ind;
        my_local = my_flat - t0;
        const float tw = (gx2 - gx1 + 1.0f) / 32.0f;
        const float th = (gy2 - gy1 + 1.0f) / 32.0f;
        stbox[tid] = make_float4(cx - fcx, cy - fcy,
                                 tw / anchors[2 * a_ind],
                                 th / anchors[2 * a_ind + 1]);
    }
    __syncthreads();   // orders: staging zeros + phase A smem before use

    // ---- issue the classes bulk stores (TMA engine; zeros source buffer) ----
    if (tid == 0) {
        asm volatile("fence.proxy.async.shared::cta;" ::: "memory");
        uint32_t saddr;
        asm("{ .reg .u64 _t; cvta.to.shared.u64 _t, %1; cvt.u32.u64 %0, _t; }"
            : "=r"(saddr) : "l"(stage));
        const char* dst = (const char*)(out + CLASSES_OFF)
                        + (long)blockIdx.x * CLS_SLICE_BYTES;
        #pragma unroll
        for (int i = 0; i < NBULK; i++)
            asm volatile("cp.async.bulk.global.shared::cta.bulk_group [%0], [%1], %2;"
                         :: "l"(dst + (long)i * STAGE_BYTES), "r"(saddr),
                            "r"((unsigned)STAGE_BYTES) : "memory");
        asm volatile("cp.async.bulk.commit_group;" ::: "memory");
    }

    // ---- phase B: scatter ownership (last index wins -> max n) ----
    if (tid < NGT && my_valid && my_local >= 0 && my_local < TPB)
        atomicMax(&swin[my_local], tid);
    __syncthreads();

    // ---- phase C: pred geometry ----
    const int hw = (t / A_) % HW_;
    const int a  = t % A_;
    const float col = (float)(hw % 40);
    const float row = (float)(hw / 40);
    const float cxp = (bp.x + col) * (1.0f / 40.0f);
    const float cyp = (bp.y + row) * (1.0f / 40.0f);
    const float bw  = bp.z * anchors[2 * a]     * (1.0f / 40.0f) * 0.5f;
    const float bh  = bp.w * anchors[2 * a + 1] * (1.0f / 40.0f) * 0.5f;
    const float x1  = (cxp - bw) * 1280.0f;
    const float y1  = (cyp - bh) * 1280.0f;
    const float x2p = (cxp + bw) * 1280.0f + 1.0f;
    const float y2p = (cyp + bh) * 1280.0f + 1.0f;
    const float sb  = 0.375f * (x2p - x1) * (y2p - y1);

    // ---- warp hull of the 32 pred boxes ----
    float hx1 = x1, hy1 = y1, hx2 = x2p, hy2 = y2p;
    #pragma unroll
    for (int s = 16; s; s >>= 1) {
        hx1 = fminf(hx1, __shfl_xor_sync(0xffffffffu, hx1, s));
        hy1 = fminf(hy1, __shfl_xor_sync(0xffffffffu, hy1, s));
        hx2 = fmaxf(hx2, __shfl_xor_sync(0xffffffffu, hx2, s));
        hy2 = fmaxf(hy2, __shfl_xor_sync(0xffffffffu, hy2, s));
    }

    // ---- candidate masks via ballot ----
    unsigned masks[4];
    #pragma unroll
    for (int j = 0; j < 4; j++) {
        const float4 g = g4[j * 32 + lane];
        const bool cand = (fminf(hx2, g.z) > fmaxf(hx1, g.x)) &&
                          (fminf(hy2, g.w) > fmaxf(hy1, g.y));
        masks[j] = __ballot_sync(0xffffffffu, cand);
    }

    // ---- hit loop over candidates only ----
    float acc = -1e30f;
    #pragma unroll
    for (int j = 0; j < 4; j++) {
        unsigned m = masks[j];
        while (m) {
            const int n = j * 32 + (__ffs(m) - 1);
            m &= m - 1;
            const float4 g = g4[n];
            const float iw = fmaxf(fminf(x2p, g.z) - fmaxf(x1, g.x), 0.0f);
            const float ih = fminf(y2p, g.w) - fmaxf(y1, g.y);
            acc = fmaxf(acc, fmaf(iw, ih, -sg[n]));
        }
    }
    const bool hit = (acc >= sb);

    // ---- fix-ups (same thread as the default writes -> ordered) ----
    const int win = swin[tid];
    if (win >= 0) {
        const float4 g = g4[win];
        const float iw = fmaxf(fminf(x2p, g.z) - fmaxf(x1, g.x), 0.0f);
        const float ih = fmaxf(fminf(y2p, g.w) - fmaxf(y1, g.y), 0.0f);
        const float inter = iw * ih;
        const float ba = (x2p - x1) * (y2p - y1);
        const float iou = inter / (ba + sga[win] - inter);
        out4[t] = stbox[win];
        out[IOUS_OFF + t] = iou;
        out[BOXM_OFF + t] = 1.0f;
        out[IOUM_OFF + t] = 5.0f * (1.0f - ip);
        out[CLSM_OFF + t] = 1.0f;
    } else if (hit) {
        out[IOUM_OFF + t] = 0.0f;
    }

    // ---- classes 1.0-set: after bulk-store completion (wait + barrier) ----
    if (tid == 0)
        asm volatile("cp.async.bulk.wait_group 0;" ::: "memory");
    __syncthreads();
    if (tid < NGT && my_valid && my_local >= 0 && my_local < TPB)
        out[CLASSES_OFF + (long)my_flat * CC + my_cls] = 1.0f;
}

extern "C" void kernel_launch(void* const* d_in, const int* in_sizes, int n_in,
                              void* d_out, int out_size)
{
    const float4* bbox4   = (const float4*)d_in[0];
    const float*  ioup    = (const float*)d_in[1];
    const float*  gtb     = (const float*)d_in[2];
    const float*  anchors = (const float*)d_in[3];
    const int*    nboxes  = (const int*)d_in[4];
    float* out = (float*)d_out;

    yolo_fused_kernel<<<NPRED / TPB, TPB>>>(bbox4, ioup, gtb, anchors, nboxes, out);
}